// round 1
// baseline (speedup 1.0000x reference)
#include <cuda_runtime.h>
#include <math.h>

#define M_TOK 16384
#define N_EMB 16384
#define KDIM  256
#define HWSZ  1024
#define NZ    (M_TOK * KDIM)   /* 4,194,304 = z element count = z_q element count */
#define FIXLEN 30.0f

// ---------------- device scratch (static, no allocation) ----------------
__device__ float g_zflat[M_TOK * KDIM];   // token-major transposed z (unscaled)
__device__ float g_enorm2[N_EMB];         // |e|^2 per codebook row
__device__ int   g_bestidx[M_TOK];        // argmin result
__device__ float g_normpart[64];          // partial sums of token norms
__device__ float g_scalars[2];            // [0]=scale, [1]=alpha = 2*scale/30
__device__ float g_diffpart[256];         // partial sums for diff

// ---------------- kernel 1: transpose z -> [tok][dim], token norms ----------------
__global__ void k_prep(const float* __restrict__ z) {
    int t  = blockIdx.x * 256 + threadIdx.x;      // 64 blocks * 256 = 16384 tokens
    int b  = t >> 10;
    int hw = t & 1023;
    const float* zp = z + (size_t)b * (KDIM * HWSZ) + hw;
    float acc = 0.0f;
#pragma unroll 4
    for (int c = 0; c < KDIM; c += 4) {
        float v0 = zp[(c + 0) * HWSZ];
        float v1 = zp[(c + 1) * HWSZ];
        float v2 = zp[(c + 2) * HWSZ];
        float v3 = zp[(c + 3) * HWSZ];
        acc += v0 * v0 + v1 * v1 + v2 * v2 + v3 * v3;
        float4 w = make_float4(v0, v1, v2, v3);
        *(float4*)&g_zflat[t * KDIM + c] = w;
    }
    float nrm = sqrtf(acc);
    __shared__ float sred[256];
    sred[threadIdx.x] = nrm;
    __syncthreads();
    for (int s = 128; s > 0; s >>= 1) {
        if (threadIdx.x < s) sred[threadIdx.x] += sred[threadIdx.x + s];
        __syncthreads();
    }
    if (threadIdx.x == 0) g_normpart[blockIdx.x] = sred[0];
}

// ---------------- kernel 2: reduce norms -> scale, alpha ----------------
__global__ void k_scale() {
    __shared__ float s[64];
    s[threadIdx.x] = g_normpart[threadIdx.x];
    __syncthreads();
    for (int st = 32; st > 0; st >>= 1) {
        if (threadIdx.x < st) s[threadIdx.x] += s[threadIdx.x + st];
        __syncthreads();
    }
    if (threadIdx.x == 0) {
        float pre_len = s[0] / (float)M_TOK;
        float scale = (pre_len >= FIXLEN) ? (FIXLEN / pre_len) : 1.0f;
        g_scalars[0] = scale;
        g_scalars[1] = 2.0f * scale / FIXLEN;
    }
}

// ---------------- kernel 3: |e|^2 per embedding row ----------------
__global__ void k_enorm(const float* __restrict__ emb) {
    int w    = threadIdx.x >> 5;
    int lane = threadIdx.x & 31;
    int r    = blockIdx.x * 8 + w;                // 2048 blocks * 8 rows
    const float4* ep = (const float4*)(emb + (size_t)r * KDIM);
    float4 a = ep[lane];
    float4 b = ep[lane + 32];
    float acc = a.x * a.x + a.y * a.y + a.z * a.z + a.w * a.w
              + b.x * b.x + b.y * b.y + b.z * b.z + b.w * b.w;
#pragma unroll
    for (int s = 16; s > 0; s >>= 1)
        acc += __shfl_down_sync(0xffffffffu, acc, s);
    if (lane == 0) g_enorm2[r] = acc;
}

// ---------------- kernel 4: fp32 GEMM (z . e^T) + fused argmin ----------------
// CTA: 128 tokens x all 16384 embeddings, K=256. 256 threads, 8x8 micro-tile.
// SMEM: As[256][PA] k-major (full K for 128 tokens), Bs[64][PB] k-major chunk,
// Es[128] = |e|^2 tile. All compute LDS are broadcast or contiguous float4.
#define PA 128
#define PB 132
#define TM 128
#define TN 128
#define KC 64

extern __shared__ float smem_g[];

__global__ void __launch_bounds__(256, 1) k_gemm(const float* __restrict__ emb) {
    float* As = smem_g;                  // 256*128 floats = 128KB
    float* Bs = smem_g + 256 * PA;       // 64*132 floats  = 33KB
    float* Es = Bs + KC * PB;            // 128 floats

    int tid = threadIdx.x;
    int tx = tid & 15;
    int ty = tid >> 4;
    int m0 = blockIdx.x * TM;

    // Fill As (once). Lanes -> consecutive m: conflict-free STS; global reads
    // uncoalesced but one-time (~1MB from L2 per CTA, negligible).
    for (int f = tid; f < TM * KDIM; f += 256) {
        int m = f & 127;
        int k = f >> 7;
        As[k * PA + m] = g_zflat[(m0 + m) * KDIM + k];
    }

    float alpha = g_scalars[1];

    float bestv[8];
    int   besti[8];
#pragma unroll
    for (int i = 0; i < 8; i++) { bestv[i] = 3.4e38f; besti[i] = 0; }

    for (int nt = 0; nt < N_EMB / TN; nt++) {
        int n0 = nt * TN;
        __syncthreads();                 // prev epilogue done reading Es
        if (tid < TN) Es[tid] = g_enorm2[n0 + tid];

        float acc[8][8];
#pragma unroll
        for (int i = 0; i < 8; i++)
#pragma unroll
            for (int j = 0; j < 8; j++) acc[i][j] = 0.0f;

        for (int kc4 = 0; kc4 < KDIM / KC; kc4++) {
            // Fill Bs chunk: lanes -> consecutive k: coalesced global reads.
            for (int f = tid; f < KC * TN; f += 256) {
                int kc = f & 63;
                int n  = f >> 6;
                Bs[kc * PB + n] = emb[(size_t)(n0 + n) * KDIM + kc4 * KC + kc];
            }
            __syncthreads();

#pragma unroll 8
            for (int kc = 0; kc < KC; kc++) {
                int k = kc4 * KC + kc;
                float4 a0 = *(const float4*)&As[k * PA + 4 * ty];
                float4 a1 = *(const float4*)&As[k * PA + 64 + 4 * ty];
                float4 b0 = *(const float4*)&Bs[kc * PB + 4 * tx];
                float4 b1 = *(const float4*)&Bs[kc * PB + 64 + 4 * tx];
                float a[8] = {a0.x, a0.y, a0.z, a0.w, a1.x, a1.y, a1.z, a1.w};
                float bb[8] = {b0.x, b0.y, b0.z, b0.w, b1.x, b1.y, b1.z, b1.w};
#pragma unroll
                for (int i = 0; i < 8; i++)
#pragma unroll
                    for (int j = 0; j < 8; j++)
                        acc[i][j] = fmaf(a[i], bb[j], acc[i][j]);
            }
            __syncthreads();             // done reading Bs before next fill
        }

        // Epilogue: d_rel = |e|^2 - alpha * (z . e); ascending n preserves
        // first-occurrence tie-breaking within a thread.
#pragma unroll
        for (int i = 0; i < 8; i++) {
#pragma unroll
            for (int j = 0; j < 8; j++) {
                int nn = (j < 4) ? (4 * tx + j) : (64 + 4 * tx + (j - 4));
                float v = Es[nn] - alpha * acc[i][j];
                int gn = n0 + nn;
                if (v < bestv[i]) { bestv[i] = v; besti[i] = gn; }
            }
        }
    }

    // Cross-thread reduction per m-row (16 candidates per row), reuse As.
    __syncthreads();
    float* Rv = As;
    int*   Ri = (int*)(As + TM * 16);
#pragma unroll
    for (int i = 0; i < 8; i++) {
        int m = (i < 4) ? (4 * ty + i) : (64 + 4 * ty + (i - 4));
        Rv[m * 16 + tx] = bestv[i];
        Ri[m * 16 + tx] = besti[i];
    }
    __syncthreads();
    if (tid < TM) {
        int m = tid;
        float bv = Rv[m * 16];
        int   bi = Ri[m * 16];
#pragma unroll
        for (int t = 1; t < 16; t++) {
            float v = Rv[m * 16 + t];
            int  ix = Ri[m * 16 + t];
            if (v < bv || (v == bv && ix < bi)) { bv = v; bi = ix; }
        }
        g_bestidx[m0 + m] = bi;
    }
}

// ---------------- kernel 5: gather z_q, write output, partial diff ----------------
__global__ void k_gather(const float* __restrict__ emb, float* __restrict__ out) {
    float scale = g_scalars[0];
    float lsum = 0.0f;
    for (int e = blockIdx.x * 256 + threadIdx.x; e < M_TOK * KDIM; e += 256 * 256) {
        int t = e >> 8;
        int c = e & 255;
        int idx = g_bestidx[t];
        float zq = emb[(size_t)idx * KDIM + c] * FIXLEN;
        float zt = g_zflat[e] * scale;
        float d = zq - zt;
        lsum += d * d;
        int b  = t >> 10;
        int hw = t & 1023;
        out[(size_t)b * (KDIM * HWSZ) + (size_t)c * HWSZ + hw] = zq;
    }
    __shared__ float sred[256];
    sred[threadIdx.x] = lsum;
    __syncthreads();
    for (int s = 128; s > 0; s >>= 1) {
        if (threadIdx.x < s) sred[threadIdx.x] += sred[threadIdx.x + s];
        __syncthreads();
    }
    if (threadIdx.x == 0) g_diffpart[blockIdx.x] = sred[0];
}

// ---------------- kernel 6: final diff + idx outputs ----------------
__global__ void k_final(float* __restrict__ out, int out_size) {
    __shared__ float s[256];
    s[threadIdx.x] = g_diffpart[threadIdx.x];
    __syncthreads();
    for (int st = 128; st > 0; st >>= 1) {
        if (threadIdx.x < st) s[threadIdx.x] += s[threadIdx.x + st];
        __syncthreads();
    }
    float diff = 0.25f * s[0] / (float)(M_TOK * KDIM);
    if (threadIdx.x == 0 && out_size > NZ) out[NZ] = diff;
    if (out_size >= NZ + 1 + M_TOK) {
        for (int t = threadIdx.x; t < M_TOK; t += 256)
            out[NZ + 1 + t] = (float)g_bestidx[t];
    }
}

// ---------------- launch ----------------
extern "C" void kernel_launch(void* const* d_in, const int* in_sizes, int n_in,
                              void* d_out, int out_size) {
    const float* z   = (const float*)d_in[0];   // [16,256,32,32]
    const float* emb = (const float*)d_in[1];   // [16384,256]
    float* out = (float*)d_out;
    (void)in_sizes; (void)n_in;

    static_assert(PA == 128 && PB == 132, "smem layout");
    const int gemm_smem = (256 * PA + KC * PB + 128) * (int)sizeof(float); // 165,376 B
    cudaFuncSetAttribute(k_gemm, cudaFuncAttributeMaxDynamicSharedMemorySize, gemm_smem);

    k_prep<<<M_TOK / 256, 256>>>(z);
    k_scale<<<1, 64>>>();
    k_enorm<<<N_EMB / 8, 256>>>(emb);
    k_gemm<<<M_TOK / TM, 256, gemm_smem>>>(emb);
    k_gather<<<256, 256>>>(emb, out);
    k_final<<<1, 256>>>(out, out_size);
}

// round 3
// speedup vs baseline: 2.7219x; 2.7219x over previous
#include <cuda_runtime.h>
#include <cuda_bf16.h>
#include <stdint.h>
#include <math.h>

#define M_TOK 16384
#define N_EMB 16384
#define KDIM  256
#define HWSZ  1024
#define NZ    (M_TOK * KDIM)
#define FIXLEN 30.0f

// ---------------- device scratch (static, no allocation) ----------------
__device__ float          g_zflat[M_TOK * KDIM];   // token-major fp32 z (unscaled)
__device__ __nv_bfloat16  g_z_hi[M_TOK * KDIM];
__device__ __nv_bfloat16  g_z_lo[M_TOK * KDIM];
__device__ __nv_bfloat16  g_e_hi[N_EMB * KDIM];
__device__ __nv_bfloat16  g_e_lo[N_EMB * KDIM];
__device__ float          g_enorm2[N_EMB];
__device__ int            g_bestidx[M_TOK];
__device__ float          g_normpart[64];
__device__ float          g_scalars[2];            // [0]=scale, [1]=alpha=2*scale/30
__device__ float          g_diffpart[256];

// ---------------- small helpers ----------------
__device__ __forceinline__ uint32_t smem_u32(const void* p) {
    uint32_t a;
    asm("{ .reg .u64 t; cvta.to.shared.u64 t, %1; cvt.u32.u64 %0, t; }" : "=r"(a) : "l"(p));
    return a;
}
__device__ __forceinline__ void cp_async16(uint32_t dst, const void* src) {
    uint64_t g = __cvta_generic_to_global(src);
    asm volatile("cp.async.cg.shared.global [%0], [%1], 16;" :: "r"(dst), "l"(g));
}
__device__ __forceinline__ void cp_commit() { asm volatile("cp.async.commit_group;"); }
template <int N> __device__ __forceinline__ void cp_wait() {
    asm volatile("cp.async.wait_group %0;" :: "n"(N));
}
__device__ __forceinline__ void ldsm_x4(uint32_t& r0, uint32_t& r1, uint32_t& r2, uint32_t& r3,
                                        uint32_t addr) {
    asm volatile("ldmatrix.sync.aligned.m8n8.x4.shared.b16 {%0,%1,%2,%3}, [%4];"
                 : "=r"(r0), "=r"(r1), "=r"(r2), "=r"(r3) : "r"(addr));
}
__device__ __forceinline__ void mma16816(float* c, uint32_t a0, uint32_t a1, uint32_t a2,
                                         uint32_t a3, uint32_t b0, uint32_t b1) {
    asm volatile("mma.sync.aligned.m16n8k16.row.col.f32.bf16.bf16.f32 "
                 "{%0,%1,%2,%3}, {%4,%5,%6,%7}, {%8,%9}, {%0,%1,%2,%3};"
                 : "+f"(c[0]), "+f"(c[1]), "+f"(c[2]), "+f"(c[3])
                 : "r"(a0), "r"(a1), "r"(a2), "r"(a3), "r"(b0), "r"(b1));
}

__device__ __forceinline__ void split4(float4 v, uint2& ph, uint2& pl) {
    __nv_bfloat16 h0 = __float2bfloat16(v.x), h1 = __float2bfloat16(v.y),
                  h2 = __float2bfloat16(v.z), h3 = __float2bfloat16(v.w);
    __nv_bfloat16 l0 = __float2bfloat16(v.x - __bfloat162float(h0));
    __nv_bfloat16 l1 = __float2bfloat16(v.y - __bfloat162float(h1));
    __nv_bfloat16 l2 = __float2bfloat16(v.z - __bfloat162float(h2));
    __nv_bfloat16 l3 = __float2bfloat16(v.w - __bfloat162float(h3));
    ph.x = (uint32_t)__bfloat16_as_ushort(h0) | ((uint32_t)__bfloat16_as_ushort(h1) << 16);
    ph.y = (uint32_t)__bfloat16_as_ushort(h2) | ((uint32_t)__bfloat16_as_ushort(h3) << 16);
    pl.x = (uint32_t)__bfloat16_as_ushort(l0) | ((uint32_t)__bfloat16_as_ushort(l1) << 16);
    pl.y = (uint32_t)__bfloat16_as_ushort(l2) | ((uint32_t)__bfloat16_as_ushort(l3) << 16);
}

// ---------------- kernel 1: transpose z, token norms, bf16 split ----------------
__global__ void k_prep(const float* __restrict__ z) {
    int t  = blockIdx.x * 256 + threadIdx.x;
    int b  = t >> 10;
    int hw = t & 1023;
    const float* zp = z + (size_t)b * (KDIM * HWSZ) + hw;
    float acc = 0.0f;
#pragma unroll 4
    for (int c = 0; c < KDIM; c += 4) {
        float v0 = zp[(c + 0) * HWSZ];
        float v1 = zp[(c + 1) * HWSZ];
        float v2 = zp[(c + 2) * HWSZ];
        float v3 = zp[(c + 3) * HWSZ];
        acc += v0 * v0 + v1 * v1 + v2 * v2 + v3 * v3;
        float4 w = make_float4(v0, v1, v2, v3);
        *(float4*)&g_zflat[t * KDIM + c] = w;
        uint2 ph, pl; split4(w, ph, pl);
        *(uint2*)&g_z_hi[t * KDIM + c] = ph;
        *(uint2*)&g_z_lo[t * KDIM + c] = pl;
    }
    float nrm = sqrtf(acc);
    __shared__ float sred[256];
    sred[threadIdx.x] = nrm;
    __syncthreads();
    for (int s = 128; s > 0; s >>= 1) {
        if (threadIdx.x < s) sred[threadIdx.x] += sred[threadIdx.x + s];
        __syncthreads();
    }
    if (threadIdx.x == 0) g_normpart[blockIdx.x] = sred[0];
}

// ---------------- kernel 2: reduce norms -> scale, alpha ----------------
__global__ void k_scale() {
    __shared__ float s[64];
    s[threadIdx.x] = g_normpart[threadIdx.x];
    __syncthreads();
    for (int st = 32; st > 0; st >>= 1) {
        if (threadIdx.x < st) s[threadIdx.x] += s[threadIdx.x + st];
        __syncthreads();
    }
    if (threadIdx.x == 0) {
        float pre_len = s[0] / (float)M_TOK;
        float scale = (pre_len >= FIXLEN) ? (FIXLEN / pre_len) : 1.0f;
        g_scalars[0] = scale;
        g_scalars[1] = 2.0f * scale / FIXLEN;
    }
}

// ---------------- kernel 3: |e|^2 (exact fp32) + bf16 split of codebook ----------------
__global__ void k_enorm(const float* __restrict__ emb) {
    int w    = threadIdx.x >> 5;
    int lane = threadIdx.x & 31;
    int r    = blockIdx.x * 8 + w;
    const float4* ep = (const float4*)(emb + (size_t)r * KDIM);
    float4 a = ep[lane];
    float4 b = ep[lane + 32];
    float acc = a.x * a.x + a.y * a.y + a.z * a.z + a.w * a.w
              + b.x * b.x + b.y * b.y + b.z * b.z + b.w * b.w;
    uint2 ph, pl;
    split4(a, ph, pl);
    *(uint2*)&g_e_hi[(size_t)r * KDIM + 4 * lane] = ph;
    *(uint2*)&g_e_lo[(size_t)r * KDIM + 4 * lane] = pl;
    split4(b, ph, pl);
    *(uint2*)&g_e_hi[(size_t)r * KDIM + 128 + 4 * lane] = ph;
    *(uint2*)&g_e_lo[(size_t)r * KDIM + 128 + 4 * lane] = pl;
#pragma unroll
    for (int s = 16; s > 0; s >>= 1)
        acc += __shfl_down_sync(0xffffffffu, acc, s);
    if (lane == 0) g_enorm2[r] = acc;
}

// ---------------- kernel 4: HMMA bf16x3 GEMM + fused argmin ----------------
// CTA = 128 tokens. A ([hi|lo], 128x512 bf16) resident in SMEM (128KB).
// Effective K = 768: chunks 0-3 = Ahi*Bhi, 4-7 = Alo*Bhi, 8-11 = Ahi*Blo.
// B streamed in 128x64 chunks, double-buffered cp.async.
// Warp grid 2(m) x 4(n); warp tile 64x32 -> 4x4 m16n8k16 per k16 step.
#define SM_A_BYTES 131072
#define SM_B_BYTES 16384

// swizzled byte offsets (XOR within 8 16B-lines) for conflict-free ldmatrix
__device__ __forceinline__ uint32_t a_sw(int row, int col) {   // col in [0,512)
    return (uint32_t)(row * 1024 + ((col >> 6) << 7)
           + (((((col >> 3) & 7) ^ (row & 7))) << 4) + ((col & 7) << 1));
}
__device__ __forceinline__ uint32_t b_sw(int row, int col) {   // col in [0,64)
    return (uint32_t)(row * 128 + ((((col >> 3) ^ (row & 7))) << 4) + ((col & 7) << 1));
}

extern __shared__ char dsm[];

__global__ void __launch_bounds__(256, 1) k_gemm_h() {
    __shared__ float Es[128];

    const int tid  = threadIdx.x;
    const int lane = tid & 31;
    const int wid  = tid >> 5;
    const int wm   = wid & 1;        // 2 warps along m
    const int wn   = wid >> 1;       // 4 warps along n
    const int m0   = blockIdx.x * 128;
    const int g    = lane >> 2;
    const int cc   = lane & 3;
    const int sub  = lane >> 3;
    const int r8   = lane & 7;

    uint32_t raw  = smem_u32(dsm);
    uint32_t base = (raw + 127u) & ~127u;
    char*    basep = dsm + (base - raw);
    const uint32_t As  = base;
    const uint32_t Bs0 = base + SM_A_BYTES;
    const uint32_t Bs1 = Bs0 + SM_B_BYTES;

    // ---- load A (hi|lo) once into SMEM ----
#pragma unroll
    for (int seg = 0; seg < 2; seg++) {
        const __nv_bfloat16* src = seg ? g_z_lo : g_z_hi;
        for (int f = tid; f < 4096; f += 256) {
            int row = f >> 5;
            int k   = (f & 31) * 8;
            cp_async16(As + a_sw(row, seg * 256 + k),
                       src + (size_t)(m0 + row) * KDIM + k);
        }
    }
    cp_commit();
    cp_wait<0>();
    __syncthreads();

    const float alpha = g_scalars[1];

    float bestv[8];
    int   besti[8];
#pragma unroll
    for (int i = 0; i < 8; i++) { bestv[i] = 3.4e38f; besti[i] = 0; }

    // per-thread constant ldmatrix row indices
    const int arow_base = wm * 64 + ((sub & 1) << 3) + r8;  // + mt*16
    const int akof      = (sub >> 1) << 3;
    const int brow_base = wn * 32 + ((sub >> 1) << 3) + r8; // + np*16
    const int bkof      = (sub & 1) << 3;

#pragma unroll 1
    for (int nt128 = 0; nt128 < 128; nt128++) {
        const int n0 = nt128 * 128;
        __syncthreads();                       // Es / B buffers free
        if (tid < 128) Es[tid] = g_enorm2[n0 + tid];

        float acc[4][4][4];
#pragma unroll
        for (int a = 0; a < 4; a++)
#pragma unroll
            for (int b = 0; b < 4; b++)
#pragma unroll
                for (int d = 0; d < 4; d++) acc[a][b][d] = 0.0f;

        // prologue: chunk 0 -> buf0
        {
            const __nv_bfloat16* src = g_e_hi;
#pragma unroll
            for (int f = tid; f < 1024; f += 256) {
                int row = f >> 3;
                int k   = (f & 7) * 8;
                cp_async16(Bs0 + b_sw(row, k), src + (size_t)(n0 + row) * KDIM + k);
            }
            cp_commit();
        }

#pragma unroll 1
        for (int c = 0; c < 12; c++) {
            const uint32_t Bcur = (c & 1) ? Bs1 : Bs0;
            if (c < 11) {
                const int cn = c + 1;
                const __nv_bfloat16* src = (cn < 8) ? g_e_hi : g_e_lo;
                const int ksrc = (cn < 8) ? (cn & 3) * 64 : (cn - 8) * 64;
                const uint32_t Bnxt = (cn & 1) ? Bs1 : Bs0;
#pragma unroll
                for (int f = tid; f < 1024; f += 256) {
                    int row = f >> 3;
                    int k   = (f & 7) * 8;
                    cp_async16(Bnxt + b_sw(row, k),
                               src + (size_t)(n0 + row) * KDIM + ksrc + k);
                }
                cp_commit();
                cp_wait<1>();
            } else {
                cp_wait<0>();
            }
            __syncthreads();

            const int acb = (c < 4) ? c * 64 : (c < 8) ? 256 + (c - 4) * 64 : (c - 8) * 64;

#pragma unroll
            for (int kk = 0; kk < 4; kk++) {
                const int acol = acb + kk * 16 + akof;
                const int bcol = kk * 16 + bkof;
                uint32_t a_r[4][4];
#pragma unroll
                for (int mt = 0; mt < 4; mt++)
                    ldsm_x4(a_r[mt][0], a_r[mt][1], a_r[mt][2], a_r[mt][3],
                            As + a_sw(arow_base + mt * 16, acol));
                uint32_t b_r[2][4];
#pragma unroll
                for (int np = 0; np < 2; np++)
                    ldsm_x4(b_r[np][0], b_r[np][1], b_r[np][2], b_r[np][3],
                            Bcur + b_sw(brow_base + np * 16, bcol));
#pragma unroll
                for (int mt = 0; mt < 4; mt++)
#pragma unroll
                    for (int nt = 0; nt < 4; nt++) {
                        const int np = nt >> 1, hp = (nt & 1) << 1;
                        mma16816(acc[mt][nt], a_r[mt][0], a_r[mt][1], a_r[mt][2],
                                 a_r[mt][3], b_r[np][hp], b_r[np][hp + 1]);
                    }
            }
            __syncthreads();
        }

        // ---- fused argmin epilogue ----
#pragma unroll
        for (int mt = 0; mt < 4; mt++) {
#pragma unroll
            for (int nt = 0; nt < 4; nt++) {
                const int nloc = wn * 32 + nt * 8 + 2 * cc;
                const float e0 = Es[nloc], e1 = Es[nloc + 1];
                float v0 = fmaf(-alpha, acc[mt][nt][0], e0);
                float v1 = fmaf(-alpha, acc[mt][nt][1], e1);
                float v2 = fmaf(-alpha, acc[mt][nt][2], e0);
                float v3 = fmaf(-alpha, acc[mt][nt][3], e1);
                const int i0 = mt * 2, i1 = mt * 2 + 1;
                const int gn = n0 + nloc;
                if (v0 < bestv[i0]) { bestv[i0] = v0; besti[i0] = gn; }
                if (v1 < bestv[i0]) { bestv[i0] = v1; besti[i0] = gn + 1; }
                if (v2 < bestv[i1]) { bestv[i1] = v2; besti[i1] = gn; }
                if (v3 < bestv[i1]) { bestv[i1] = v3; besti[i1] = gn + 1; }
            }
        }
    }

    // ---- final per-row reduction (16 candidates per row), reuse A smem ----
    __syncthreads();
    float* Rv = (float*)basep;
    int*   Ri = (int*)(basep + 128 * 16 * sizeof(float));
    const int slot = wn * 4 + cc;
#pragma unroll
    for (int mt = 0; mt < 4; mt++) {
#pragma unroll
        for (int h = 0; h < 2; h++) {
            int mloc = wm * 64 + mt * 16 + 8 * h + g;
            Rv[mloc * 16 + slot] = bestv[mt * 2 + h];
            Ri[mloc * 16 + slot] = besti[mt * 2 + h];
        }
    }
    __syncthreads();
    if (tid < 128) {
        float bv = Rv[tid * 16];
        int   bi = Ri[tid * 16];
#pragma unroll
        for (int t = 1; t < 16; t++) {
            float v = Rv[tid * 16 + t];
            int  ix = Ri[tid * 16 + t];
            if (v < bv || (v == bv && ix < bi)) { bv = v; bi = ix; }
        }
        g_bestidx[m0 + tid] = bi;
    }
}

// ---------------- kernel 5: gather z_q, write output, partial diff ----------------
__global__ void k_gather(const float* __restrict__ emb, float* __restrict__ out) {
    float scale = g_scalars[0];
    float lsum = 0.0f;
    for (int e = blockIdx.x * 256 + threadIdx.x; e < M_TOK * KDIM; e += 256 * 256) {
        int t = e >> 8;
        int c = e & 255;
        int idx = g_bestidx[t];
        float zq = emb[(size_t)idx * KDIM + c] * FIXLEN;
        float zt = g_zflat[e] * scale;
        float d = zq - zt;
        lsum += d * d;
        int b  = t >> 10;
        int hw = t & 1023;
        out[(size_t)b * (KDIM * HWSZ) + (size_t)c * HWSZ + hw] = zq;
    }
    __shared__ float sred[256];
    sred[threadIdx.x] = lsum;
    __syncthreads();
    for (int s = 128; s > 0; s >>= 1) {
        if (threadIdx.x < s) sred[threadIdx.x] += sred[threadIdx.x + s];
        __syncthreads();
    }
    if (threadIdx.x == 0) g_diffpart[blockIdx.x] = sred[0];
}

// ---------------- kernel 6: final diff + idx outputs ----------------
__global__ void k_final(float* __restrict__ out, int out_size) {
    __shared__ float s[256];
    s[threadIdx.x] = g_diffpart[threadIdx.x];
    __syncthreads();
    for (int st = 128; st > 0; st >>= 1) {
        if (threadIdx.x < st) s[threadIdx.x] += s[threadIdx.x + st];
        __syncthreads();
    }
    float diff = 0.25f * s[0] / (float)(M_TOK * KDIM);
    if (threadIdx.x == 0 && out_size > NZ) out[NZ] = diff;
    if (out_size >= NZ + 1 + M_TOK) {
        for (int t = threadIdx.x; t < M_TOK; t += 256)
            out[NZ + 1 + t] = (float)g_bestidx[t];
    }
}

// ---------------- launch ----------------
extern "C" void kernel_launch(void* const* d_in, const int* in_sizes, int n_in,
                              void* d_out, int out_size) {
    const float* z   = (const float*)d_in[0];
    const float* emb = (const float*)d_in[1];
    float* out = (float*)d_out;
    (void)in_sizes; (void)n_in;

    const int gemm_smem = 256 + SM_A_BYTES + 2 * SM_B_BYTES;  // 164,096 B
    cudaFuncSetAttribute(k_gemm_h, cudaFuncAttributeMaxDynamicSharedMemorySize, gemm_smem);

    k_prep<<<M_TOK / 256, 256>>>(z);
    k_scale<<<1, 64>>>();
    k_enorm<<<N_EMB / 8, 256>>>(emb);
    k_gemm_h<<<M_TOK / 128, 256, gemm_smem>>>();
    k_gather<<<256, 256>>>(emb, out);
    k_final<<<1, 256>>>(out, out_size);
}

// round 4
// speedup vs baseline: 3.0171x; 1.1084x over previous
#include <cuda_runtime.h>
#include <cuda_bf16.h>
#include <stdint.h>
#include <math.h>

#define M_TOK 16384
#define N_EMB 16384
#define KDIM  256
#define HWSZ  1024
#define NZ    (M_TOK * KDIM)
#define FIXLEN 30.0f

// ---------------- device scratch (static, no allocation) ----------------
__device__ float          g_zflat[M_TOK * KDIM];
__device__ __nv_bfloat16  g_z_hi[M_TOK * KDIM];
__device__ __nv_bfloat16  g_z_lo[M_TOK * KDIM];
__device__ __nv_bfloat16  g_e_hi[N_EMB * KDIM];
__device__ __nv_bfloat16  g_e_lo[N_EMB * KDIM];
__device__ float          g_enorm2[N_EMB];
__device__ int            g_bestidx[M_TOK];
__device__ float          g_normpart[64];
__device__ float          g_scalars[2];
__device__ float          g_diffpart[256];

// ---------------- small helpers ----------------
__device__ __forceinline__ uint32_t smem_u32(const void* p) {
    uint32_t a;
    asm("{ .reg .u64 t; cvta.to.shared.u64 t, %1; cvt.u32.u64 %0, t; }" : "=r"(a) : "l"(p));
    return a;
}
__device__ __forceinline__ void cp_async16(uint32_t dst, const void* src) {
    uint64_t g = __cvta_generic_to_global(src);
    asm volatile("cp.async.cg.shared.global [%0], [%1], 16;" :: "r"(dst), "l"(g));
}
__device__ __forceinline__ void cp_commit() { asm volatile("cp.async.commit_group;"); }
template <int N> __device__ __forceinline__ void cp_wait() {
    asm volatile("cp.async.wait_group %0;" :: "n"(N));
}
__device__ __forceinline__ void ldsm4(uint32_t* r, uint32_t addr) {
    asm volatile("ldmatrix.sync.aligned.m8n8.x4.shared.b16 {%0,%1,%2,%3}, [%4];"
                 : "=r"(r[0]), "=r"(r[1]), "=r"(r[2]), "=r"(r[3]) : "r"(addr));
}
__device__ __forceinline__ void mma16816(float* c, const uint32_t* a, uint32_t b0, uint32_t b1) {
    asm volatile("mma.sync.aligned.m16n8k16.row.col.f32.bf16.bf16.f32 "
                 "{%0,%1,%2,%3}, {%4,%5,%6,%7}, {%8,%9}, {%0,%1,%2,%3};"
                 : "+f"(c[0]), "+f"(c[1]), "+f"(c[2]), "+f"(c[3])
                 : "r"(a[0]), "r"(a[1]), "r"(a[2]), "r"(a[3]), "r"(b0), "r"(b1));
}

__device__ __forceinline__ void split4(float4 v, uint2& ph, uint2& pl) {
    __nv_bfloat16 h0 = __float2bfloat16(v.x), h1 = __float2bfloat16(v.y),
                  h2 = __float2bfloat16(v.z), h3 = __float2bfloat16(v.w);
    __nv_bfloat16 l0 = __float2bfloat16(v.x - __bfloat162float(h0));
    __nv_bfloat16 l1 = __float2bfloat16(v.y - __bfloat162float(h1));
    __nv_bfloat16 l2 = __float2bfloat16(v.z - __bfloat162float(h2));
    __nv_bfloat16 l3 = __float2bfloat16(v.w - __bfloat162float(h3));
    ph.x = (uint32_t)__bfloat16_as_ushort(h0) | ((uint32_t)__bfloat16_as_ushort(h1) << 16);
    ph.y = (uint32_t)__bfloat16_as_ushort(h2) | ((uint32_t)__bfloat16_as_ushort(h3) << 16);
    pl.x = (uint32_t)__bfloat16_as_ushort(l0) | ((uint32_t)__bfloat16_as_ushort(l1) << 16);
    pl.y = (uint32_t)__bfloat16_as_ushort(l2) | ((uint32_t)__bfloat16_as_ushort(l3) << 16);
}

// ---------------- kernel 1: transpose z, token norms, bf16 split ----------------
__global__ void k_prep(const float* __restrict__ z) {
    int t  = blockIdx.x * 256 + threadIdx.x;
    int b  = t >> 10;
    int hw = t & 1023;
    const float* zp = z + (size_t)b * (KDIM * HWSZ) + hw;
    float acc = 0.0f;
#pragma unroll 4
    for (int c = 0; c < KDIM; c += 4) {
        float v0 = zp[(c + 0) * HWSZ];
        float v1 = zp[(c + 1) * HWSZ];
        float v2 = zp[(c + 2) * HWSZ];
        float v3 = zp[(c + 3) * HWSZ];
        acc += v0 * v0 + v1 * v1 + v2 * v2 + v3 * v3;
        float4 w = make_float4(v0, v1, v2, v3);
        *(float4*)&g_zflat[t * KDIM + c] = w;
        uint2 ph, pl; split4(w, ph, pl);
        *(uint2*)&g_z_hi[t * KDIM + c] = ph;
        *(uint2*)&g_z_lo[t * KDIM + c] = pl;
    }
    float nrm = sqrtf(acc);
    __shared__ float sred[256];
    sred[threadIdx.x] = nrm;
    __syncthreads();
    for (int s = 128; s > 0; s >>= 1) {
        if (threadIdx.x < s) sred[threadIdx.x] += sred[threadIdx.x + s];
        __syncthreads();
    }
    if (threadIdx.x == 0) g_normpart[blockIdx.x] = sred[0];
}

// ---------------- kernel 2 ----------------
__global__ void k_scale() {
    __shared__ float s[64];
    s[threadIdx.x] = g_normpart[threadIdx.x];
    __syncthreads();
    for (int st = 32; st > 0; st >>= 1) {
        if (threadIdx.x < st) s[threadIdx.x] += s[threadIdx.x + st];
        __syncthreads();
    }
    if (threadIdx.x == 0) {
        float pre_len = s[0] / (float)M_TOK;
        float scale = (pre_len >= FIXLEN) ? (FIXLEN / pre_len) : 1.0f;
        g_scalars[0] = scale;
        g_scalars[1] = 2.0f * scale / FIXLEN;
    }
}

// ---------------- kernel 3 ----------------
__global__ void k_enorm(const float* __restrict__ emb) {
    int w    = threadIdx.x >> 5;
    int lane = threadIdx.x & 31;
    int r    = blockIdx.x * 8 + w;
    const float4* ep = (const float4*)(emb + (size_t)r * KDIM);
    float4 a = ep[lane];
    float4 b = ep[lane + 32];
    float acc = a.x * a.x + a.y * a.y + a.z * a.z + a.w * a.w
              + b.x * b.x + b.y * b.y + b.z * b.z + b.w * b.w;
    uint2 ph, pl;
    split4(a, ph, pl);
    *(uint2*)&g_e_hi[(size_t)r * KDIM + 4 * lane] = ph;
    *(uint2*)&g_e_lo[(size_t)r * KDIM + 4 * lane] = pl;
    split4(b, ph, pl);
    *(uint2*)&g_e_hi[(size_t)r * KDIM + 128 + 4 * lane] = ph;
    *(uint2*)&g_e_lo[(size_t)r * KDIM + 128 + 4 * lane] = pl;
#pragma unroll
    for (int s = 16; s > 0; s >>= 1)
        acc += __shfl_down_sync(0xffffffffu, acc, s);
    if (lane == 0) g_enorm2[r] = acc;
}

// ---------------- kernel 4: HMMA bf16x3 GEMM + fused argmin ----------------
// 512 threads, warp grid 4(m) x 4(n), warp tile 32x32.
// A (128 tok x [hi|lo] 512 cols bf16) resident in SMEM (128KB).
// B: 4 chunks/n-iter of 128n x 128k (ehi k0, ehi k1, elo k0, elo k1),
// triple-buffered cp.async, ONE __syncthreads per chunk; e_hi chunks feed
// two A passes (hi and lo). Register-pipelined ldmatrix.
#define SM_A_BYTES 131072
#define SM_B_BYTES 32768

__device__ __forceinline__ uint32_t a_sw(int row, int col) {   // col in [0,512)
    return (uint32_t)(row * 1024 + ((col >> 6) << 7)
           + (((((col >> 3) & 7) ^ (row & 7))) << 4) + ((col & 7) << 1));
}
__device__ __forceinline__ uint32_t b_sw(int row, int col) {   // col in [0,128)
    return (uint32_t)(row * 256 + ((col >> 6) << 7)
           + (((((col >> 3) & 7) ^ (row & 7))) << 4) + ((col & 7) << 1));
}

extern __shared__ char dsm[];

__device__ __forceinline__ void compute_pass(
    uint32_t As, uint32_t Bb, int abase,
    int arow_base, int akof, int brow_base, int bkof,
    float acc[2][4][4])
{
    uint32_t a_r[2][2][4];
    uint32_t b_r[2][2][4];
#pragma unroll
    for (int mt = 0; mt < 2; mt++)
        ldsm4(a_r[0][mt], As + a_sw(arow_base + mt * 16, abase + akof));
#pragma unroll
    for (int np = 0; np < 2; np++)
        ldsm4(b_r[0][np], Bb + b_sw(brow_base + np * 16, bkof));
#pragma unroll
    for (int kk = 0; kk < 8; kk++) {
        const int cur = kk & 1, nxt = cur ^ 1;
        if (kk < 7) {
            const int acol = abase + (kk + 1) * 16 + akof;
            const int bcol = (kk + 1) * 16 + bkof;
#pragma unroll
            for (int mt = 0; mt < 2; mt++)
                ldsm4(a_r[nxt][mt], As + a_sw(arow_base + mt * 16, acol));
#pragma unroll
            for (int np = 0; np < 2; np++)
                ldsm4(b_r[nxt][np], Bb + b_sw(brow_base + np * 16, bcol));
        }
#pragma unroll
        for (int mt = 0; mt < 2; mt++)
#pragma unroll
            for (int nt = 0; nt < 4; nt++)
                mma16816(acc[mt][nt], a_r[cur][mt],
                         b_r[cur][nt >> 1][(nt & 1) * 2],
                         b_r[cur][nt >> 1][(nt & 1) * 2 + 1]);
    }
}

__global__ void __launch_bounds__(512, 1) k_gemm_h() {
    __shared__ float Es[128];

    const int tid  = threadIdx.x;
    const int lane = tid & 31;
    const int wid  = tid >> 5;
    const int wm   = wid & 3;        // 4 warps along m
    const int wn   = wid >> 2;       // 4 warps along n
    const int m0   = blockIdx.x * 128;
    const int g    = lane >> 2;
    const int cc   = lane & 3;
    const int sub  = lane >> 3;
    const int r8   = lane & 7;

    uint32_t raw  = smem_u32(dsm);
    uint32_t base = (raw + 255u) & ~255u;
    char*    basep = dsm + (base - raw);
    const uint32_t As = base;
    const uint32_t Bbuf0 = base + SM_A_BYTES;

    // ---- load A (hi|lo) once ----
#pragma unroll
    for (int seg = 0; seg < 2; seg++) {
        const __nv_bfloat16* src = seg ? g_z_lo : g_z_hi;
        for (int f = tid; f < 4096; f += 512) {
            int row = f >> 5;
            int k   = (f & 31) * 8;
            cp_async16(As + a_sw(row, seg * 256 + k),
                       src + (size_t)(m0 + row) * KDIM + k);
        }
    }
    cp_commit();
    cp_wait<0>();
    __syncthreads();

    const float alpha = g_scalars[1];

    float bestv[4];
    int   besti[4];
#pragma unroll
    for (int i = 0; i < 4; i++) { bestv[i] = 3.4e38f; besti[i] = 0; }

    const int arow_base = wm * 32 + ((sub & 1) << 3) + r8;   // + mt*16
    const int akof      = (sub >> 1) << 3;
    const int brow_base = wn * 32 + ((sub >> 1) << 3) + r8;  // + np*16
    const int bkof      = (sub & 1) << 3;

#pragma unroll 1
    for (int nt128 = 0; nt128 < 128; nt128++) {
        const int n0 = nt128 * 128;
        __syncthreads();                    // Es free; buf0/buf1 free
        if (tid < 128) Es[tid] = g_enorm2[n0 + tid];

        // prologue: chunks 0 (e_hi k0) and 1 (e_hi k128)
#pragma unroll
        for (int c = 0; c < 2; c++) {
            const __nv_bfloat16* src = g_e_hi;
            const uint32_t dst = Bbuf0 + c * SM_B_BYTES;
            for (int f = tid; f < 2048; f += 512) {
                int row = f >> 4;
                int k   = (f & 15) * 8;
                cp_async16(dst + b_sw(row, k),
                           src + (size_t)(n0 + row) * KDIM + c * 128 + k);
            }
            cp_commit();
        }

        float acc[2][4][4];
#pragma unroll
        for (int a = 0; a < 2; a++)
#pragma unroll
            for (int b = 0; b < 4; b++)
#pragma unroll
                for (int d = 0; d < 4; d++) acc[a][b][d] = 0.0f;

#pragma unroll
        for (int bc = 0; bc < 4; bc++) {
            if (bc < 3) cp_wait<1>(); else cp_wait<0>();
            __syncthreads();
            if (bc < 2) {
                // issue chunk bc+2 (= e_lo, kbase (bc)*128) into buf (bc+2)%3
                const __nv_bfloat16* src = g_e_lo;
                const uint32_t dst = Bbuf0 + ((bc + 2) % 3) * SM_B_BYTES;
                for (int f = tid; f < 2048; f += 512) {
                    int row = f >> 4;
                    int k   = (f & 15) * 8;
                    cp_async16(dst + b_sw(row, k),
                               src + (size_t)(n0 + row) * KDIM + bc * 128 + k);
                }
                cp_commit();
            }
            const uint32_t Bb = Bbuf0 + (bc % 3) * SM_B_BYTES;
            // pass 1: A = z_hi block (cols (bc&1)*128)
            compute_pass(As, Bb, (bc & 1) * 128, arow_base, akof, brow_base, bkof, acc);
            // pass 2 (only for e_hi chunks): A = z_lo block (cols 256 + bc*128)
            if (bc < 2)
                compute_pass(As, Bb, 256 + bc * 128, arow_base, akof, brow_base, bkof, acc);
        }

        // ---- fused argmin epilogue ----
#pragma unroll
        for (int mt = 0; mt < 2; mt++) {
#pragma unroll
            for (int nt = 0; nt < 4; nt++) {
                const int nloc = wn * 32 + nt * 8 + 2 * cc;
                const float e0 = Es[nloc], e1 = Es[nloc + 1];
                float v0 = fmaf(-alpha, acc[mt][nt][0], e0);
                float v1 = fmaf(-alpha, acc[mt][nt][1], e1);
                float v2 = fmaf(-alpha, acc[mt][nt][2], e0);
                float v3 = fmaf(-alpha, acc[mt][nt][3], e1);
                const int i0 = mt * 2, i1 = mt * 2 + 1;
                const int gn = n0 + nloc;
                if (v0 < bestv[i0]) { bestv[i0] = v0; besti[i0] = gn; }
                if (v1 < bestv[i0]) { bestv[i0] = v1; besti[i0] = gn + 1; }
                if (v2 < bestv[i1]) { bestv[i1] = v2; besti[i1] = gn; }
                if (v3 < bestv[i1]) { bestv[i1] = v3; besti[i1] = gn + 1; }
            }
        }
    }

    // ---- final per-row reduction (16 candidates per row) ----
    __syncthreads();
    float* Rv = (float*)basep;
    int*   Ri = (int*)(basep + 128 * 16 * sizeof(float));
    const int slot = wn * 4 + cc;
#pragma unroll
    for (int mt = 0; mt < 2; mt++) {
#pragma unroll
        for (int h = 0; h < 2; h++) {
            int mloc = wm * 32 + mt * 16 + h * 8 + g;
            Rv[mloc * 16 + slot] = bestv[mt * 2 + h];
            Ri[mloc * 16 + slot] = besti[mt * 2 + h];
        }
    }
    __syncthreads();
    if (tid < 128) {
        float bv = Rv[tid * 16];
        int   bi = Ri[tid * 16];
#pragma unroll
        for (int t = 1; t < 16; t++) {
            float v = Rv[tid * 16 + t];
            int  ix = Ri[tid * 16 + t];
            if (v < bv || (v == bv && ix < bi)) { bv = v; bi = ix; }
        }
        g_bestidx[m0 + tid] = bi;
    }
}

// ---------------- kernel 5 ----------------
__global__ void k_gather(const float* __restrict__ emb, float* __restrict__ out) {
    float scale = g_scalars[0];
    float lsum = 0.0f;
    for (int e = blockIdx.x * 256 + threadIdx.x; e < M_TOK * KDIM; e += 256 * 256) {
        int t = e >> 8;
        int c = e & 255;
        int idx = g_bestidx[t];
        float zq = emb[(size_t)idx * KDIM + c] * FIXLEN;
        float zt = g_zflat[e] * scale;
        float d = zq - zt;
        lsum += d * d;
        int b  = t >> 10;
        int hw = t & 1023;
        out[(size_t)b * (KDIM * HWSZ) + (size_t)c * HWSZ + hw] = zq;
    }
    __shared__ float sred[256];
    sred[threadIdx.x] = lsum;
    __syncthreads();
    for (int s = 128; s > 0; s >>= 1) {
        if (threadIdx.x < s) sred[threadIdx.x] += sred[threadIdx.x + s];
        __syncthreads();
    }
    if (threadIdx.x == 0) g_diffpart[blockIdx.x] = sred[0];
}

// ---------------- kernel 6 ----------------
__global__ void k_final(float* __restrict__ out, int out_size) {
    __shared__ float s[256];
    s[threadIdx.x] = g_diffpart[threadIdx.x];
    __syncthreads();
    for (int st = 128; st > 0; st >>= 1) {
        if (threadIdx.x < st) s[threadIdx.x] += s[threadIdx.x + st];
        __syncthreads();
    }
    float diff = 0.25f * s[0] / (float)(M_TOK * KDIM);
    if (threadIdx.x == 0 && out_size > NZ) out[NZ] = diff;
    if (out_size >= NZ + 1 + M_TOK) {
        for (int t = threadIdx.x; t < M_TOK; t += 256)
            out[NZ + 1 + t] = (float)g_bestidx[t];
    }
}

// ---------------- launch ----------------
extern "C" void kernel_launch(void* const* d_in, const int* in_sizes, int n_in,
                              void* d_out, int out_size) {
    const float* z   = (const float*)d_in[0];
    const float* emb = (const float*)d_in[1];
    float* out = (float*)d_out;
    (void)in_sizes; (void)n_in;

    const int gemm_smem = 256 + SM_A_BYTES + 3 * SM_B_BYTES;  // 229,632 B
    cudaFuncSetAttribute(k_gemm_h, cudaFuncAttributeMaxDynamicSharedMemorySize, gemm_smem);

    k_prep<<<M_TOK / 256, 256>>>(z);
    k_scale<<<1, 64>>>();
    k_enorm<<<N_EMB / 8, 256>>>(emb);
    k_gemm_h<<<M_TOK / 128, 512, gemm_smem>>>();
    k_gather<<<256, 256>>>(emb, out);
    k_final<<<1, 256>>>(out, out_size);
}